// round 2
// baseline (speedup 1.0000x reference)
#include <cuda_runtime.h>
#include <cuda_bf16.h>
#include <cstdint>

// HistogramLoss, fused single-kernel version.
//   Per (b,c) row: 64-bin histogram over [0,1], normalized by exactly HW=262144.
//   loss = sum_bins |count_fake - count_real| / (HW * ROWS * BINS)
//   Signed accumulation: +1 fake, -1 real. Last CTA (ticket) does the final
//   abs-sum reduction and self-restores all device state for graph replay.

#define ROWS      96                   // 32*3
#define BINS      64
#define HW        262144               // 512*512
#define CHUNKS    8                    // chunks per row per source
#define CHUNK     (HW / CHUNKS)        // 32768 elements
#define THREADS   256
#define NWARP     (THREADS / 32)
#define SUBS      (NWARP * 2)          // 2 sub-histograms per warp (lane parity)
#define PER_TH    (CHUNK / THREADS)    // 128 elements = 32 float4
#define GRID      (ROWS * 2 * CHUNKS)  // 1536 CTAs

__device__ int g_hist[ROWS * BINS];    // zero at load; last CTA re-zeroes.
__device__ unsigned int g_counter;     // zero at load; last CTA resets.

__global__ __launch_bounds__(THREADS, 8)
void hist_fused_kernel(const float* __restrict__ fake,
                       const float* __restrict__ real,
                       float* __restrict__ out) {
    __shared__ int sh[SUBS][BINS];
    __shared__ int s_last;
    __shared__ int warp_sums[NWARP];

    const int tid  = threadIdx.x;
    const int wid  = tid >> 5;
    const int lane = tid & 31;

    // ---- decode block: [src][row][chunk] ----
    int id    = blockIdx.x;
    int src   = id >= (ROWS * CHUNKS);
    int r2    = id - src * (ROWS * CHUNKS);
    int row   = r2 >> 3;              // / CHUNKS
    int chunk = r2 & (CHUNKS - 1);

    // ---- zero shared sub-histograms ----
    #pragma unroll
    for (int i = tid; i < SUBS * BINS; i += THREADS)
        ((int*)sh)[i] = 0;
    __syncthreads();

    const float* base = (src ? real : fake) + (size_t)row * HW + (size_t)chunk * CHUNK;
    const float4* p   = (const float4*)base;

    int* myh = sh[wid * 2 + (lane & 1)];   // lane-parity split halves conflicts

    #pragma unroll 4
    for (int i = 0; i < PER_TH / 4; i++) {
        float4 v = p[i * THREADS + tid];

        int b0 = (int)(v.x * 64.0f);
        int b1 = (int)(v.y * 64.0f);
        int b2 = (int)(v.z * 64.0f);
        int b3 = (int)(v.w * 64.0f);
        b0 = min(max(b0, 0), 63);
        b1 = min(max(b1, 0), 63);
        b2 = min(max(b2, 0), 63);
        b3 = min(max(b3, 0), 63);

        atomicAdd(&myh[b0], 1);
        atomicAdd(&myh[b1], 1);
        atomicAdd(&myh[b2], 1);
        atomicAdd(&myh[b3], 1);
    }
    __syncthreads();

    // ---- flush: 64 threads sum across SUBS sub-histograms ----
    if (tid < BINS) {
        int total = 0;
        #pragma unroll
        for (int s = 0; s < SUBS; s++)
            total += sh[s][tid];
        if (src) total = -total;
        atomicAdd(&g_hist[row * BINS + tid], total);
    }
    __syncthreads();

    // ---- last-block-done ticket ----
    if (tid == 0) {
        __threadfence();
        unsigned int t = atomicAdd(&g_counter, 1u);
        s_last = (t == GRID - 1);
    }
    __syncthreads();
    if (!s_last) return;

    // ---- final reduction (last CTA only) ----
    int acc = 0;
    #pragma unroll 4
    for (int i = tid; i < ROWS * BINS; i += THREADS) {
        int h = __ldcg(&g_hist[i]);    // L2 load: sees all prior atomics
        g_hist[i] = 0;                 // self-restore for next graph replay
        acc += (h < 0) ? -h : h;
    }
    #pragma unroll
    for (int off = 16; off > 0; off >>= 1)
        acc += __shfl_down_sync(0xFFFFFFFFu, acc, off);
    if (lane == 0) warp_sums[wid] = acc;
    __syncthreads();
    if (tid == 0) {
        int total = 0;
        #pragma unroll
        for (int w = 0; w < NWARP; w++)
            total += warp_sums[w];
        out[0] = (float)total * (1.0f / (262144.0f * 6144.0f));
        g_counter = 0;                 // self-restore
    }
}

extern "C" void kernel_launch(void* const* d_in, const int* in_sizes, int n_in,
                              void* d_out, int out_size) {
    const float* fake = (const float*)d_in[0];
    const float* real = (const float*)d_in[1];
    float* out = (float*)d_out;

    hist_fused_kernel<<<GRID, THREADS>>>(fake, real, out);
}

// round 3
// speedup vs baseline: 1.0621x; 1.0621x over previous
#include <cuda_runtime.h>
#include <cuda_bf16.h>
#include <cstdint>

// HistogramLoss, fused single-kernel.
//   Per (b,c) row: 64-bin histogram over [0,1]; both normalizers are exactly
//   HW=262144, so accumulate one signed histogram (+1 fake, -1 real).
//   loss = sum_bins |count_fake - count_real| / (HW * ROWS * BINS)
//   Last CTA (ticket) reduces and self-restores device state for graph replay.

#define ROWS      96                   // 32*3
#define BINS      64
#define HW        262144               // 512*512
#define CHUNKS    8                    // chunks per row per source
#define CHUNK     (HW / CHUNKS)        // 32768 elements
#define THREADS   256
#define NWARP     (THREADS / 32)
#define PER_TH    (CHUNK / THREADS)    // 128 elements = 32 float4
#define GRID      (ROWS * 2 * CHUNKS)  // 1536 CTAs

__device__ int g_hist[ROWS * BINS];    // zero at load; last CTA re-zeroes.
__device__ unsigned int g_counter;     // zero at load; last CTA resets.

__global__ __launch_bounds__(THREADS)
void hist_fused_kernel(const float* __restrict__ fake,
                       const float* __restrict__ real,
                       float* __restrict__ out) {
    __shared__ int sh[NWARP][BINS];    // one sub-histogram per warp (R1 layout)
    __shared__ int s_last;
    __shared__ int warp_sums[NWARP];

    const int tid  = threadIdx.x;
    const int wid  = tid >> 5;
    const int lane = tid & 31;

    // ---- decode block: [src][row][chunk] ----
    int id    = blockIdx.x;
    int src   = id >= (ROWS * CHUNKS);
    int r2    = id - src * (ROWS * CHUNKS);
    int row   = r2 >> 3;              // / CHUNKS
    int chunk = r2 & (CHUNKS - 1);

    // ---- zero shared sub-histograms ----
    #pragma unroll
    for (int i = tid; i < NWARP * BINS; i += THREADS)
        ((int*)sh)[i] = 0;
    __syncthreads();

    const float* base = (src ? real : fake) + (size_t)row * HW + (size_t)chunk * CHUNK;
    const float4* p   = (const float4*)base;

    int* myh = sh[wid];

    #pragma unroll 4
    for (int i = 0; i < PER_TH / 4; i++) {
        float4 v = __ldcs(&p[i * THREADS + tid]);   // streaming: read-once data

        int b0 = (int)(v.x * 64.0f);
        int b1 = (int)(v.y * 64.0f);
        int b2 = (int)(v.z * 64.0f);
        int b3 = (int)(v.w * 64.0f);
        b0 = min(max(b0, 0), 63);
        b1 = min(max(b1, 0), 63);
        b2 = min(max(b2, 0), 63);
        b3 = min(max(b3, 0), 63);

        atomicAdd(&myh[b0], 1);
        atomicAdd(&myh[b1], 1);
        atomicAdd(&myh[b2], 1);
        atomicAdd(&myh[b3], 1);
    }
    __syncthreads();

    // ---- flush: 64 threads sum across NWARP sub-histograms ----
    if (tid < BINS) {
        int total = 0;
        #pragma unroll
        for (int w = 0; w < NWARP; w++)
            total += sh[w][tid];
        if (src) total = -total;
        atomicAdd(&g_hist[row * BINS + tid], total);
    }
    __syncthreads();

    // ---- last-block-done ticket ----
    if (tid == 0) {
        __threadfence();
        unsigned int t = atomicAdd(&g_counter, 1u);
        s_last = (t == GRID - 1);
    }
    __syncthreads();
    if (!s_last) return;

    // ---- final reduction (last CTA only) ----
    int acc = 0;
    #pragma unroll 4
    for (int i = tid; i < ROWS * BINS; i += THREADS) {
        int h = __ldcg(&g_hist[i]);    // L2 load: sees all prior atomics
        g_hist[i] = 0;                 // self-restore for next graph replay
        acc += (h < 0) ? -h : h;
    }
    #pragma unroll
    for (int off = 16; off > 0; off >>= 1)
        acc += __shfl_down_sync(0xFFFFFFFFu, acc, off);
    if (lane == 0) warp_sums[wid] = acc;
    __syncthreads();
    if (tid == 0) {
        int total = 0;
        #pragma unroll
        for (int w = 0; w < NWARP; w++)
            total += warp_sums[w];
        out[0] = (float)total * (1.0f / (262144.0f * 6144.0f));
        g_counter = 0;                 // self-restore
    }
}

extern "C" void kernel_launch(void* const* d_in, const int* in_sizes, int n_in,
                              void* d_out, int out_size) {
    const float* fake = (const float*)d_in[0];
    const float* real = (const float*)d_in[1];
    float* out = (float*)d_out;

    hist_fused_kernel<<<GRID, THREADS>>>(fake, real, out);
}